// round 1
// baseline (speedup 1.0000x reference)
#include <cuda_runtime.h>
#include <math.h>

// Problem constants
#define BB 4
#define TT 2048
#define CC 1024
#define HH 16
#define DD 64
#define MTOT (BB * TT)          // 8192

// Scratch (allocation is banned -> __device__ globals)
__device__ float g_Q[BB * HH * TT * DD];
__device__ float g_K[BB * HH * TT * DD];
__device__ float g_V[BB * HH * TT * DD];
__device__ float g_Y[BB * TT * CC];

// ---------------------------------------------------------------------------
// SGEMM: C[M,N] = A[M,K] @ B[K,N], 128x128 block tile, BK=8, 8x8 microtile.
// MODE 0: scatter epilogue into g_Q/g_K/g_V ([B,H,T,D] layout), C unused.
// MODE 1: plain store to C.
// ---------------------------------------------------------------------------
template <int MODE>
__global__ __launch_bounds__(256) void sgemm_kernel(
    const float* __restrict__ A, const float* __restrict__ Bm,
    float* __restrict__ C, int M, int N, int K)
{
    __shared__ float As[8][128];
    __shared__ float Bs[8][128];

    const int tid = threadIdx.x;
    const int bm = blockIdx.y * 128;
    const int bn = blockIdx.x * 128;

    // Global load assignments (all dims divide evenly; no bounds checks)
    const int arow = tid >> 1;            // 0..127
    const int acol4 = (tid & 1) * 4;      // 0 or 4
    const int brow = tid >> 5;            // 0..7
    const int bcol4 = (tid & 31) * 4;     // 0..124

    const float* Aptr = A + (size_t)(bm + arow) * K + acol4;
    const float* Bptr = Bm + (size_t)brow * N + bn + bcol4;

    const int tx = tid & 15;              // col group
    const int ty = tid >> 4;              // row group

    float acc[8][8];
#pragma unroll
    for (int i = 0; i < 8; i++)
#pragma unroll
        for (int j = 0; j < 8; j++) acc[i][j] = 0.0f;

    for (int k0 = 0; k0 < K; k0 += 8) {
        float4 av = *(const float4*)Aptr;
        float4 bv = *(const float4*)Bptr;
        Aptr += 8;
        Bptr += (size_t)8 * N;

        __syncthreads();  // previous iteration's consumers done
        As[acol4 + 0][arow] = av.x;
        As[acol4 + 1][arow] = av.y;
        As[acol4 + 2][arow] = av.z;
        As[acol4 + 3][arow] = av.w;
        *(float4*)&Bs[brow][bcol4] = bv;
        __syncthreads();

#pragma unroll
        for (int kk = 0; kk < 8; kk++) {
            float ra[8], rb[8];
            float4 a0 = *(const float4*)&As[kk][ty * 8];
            float4 a1 = *(const float4*)&As[kk][ty * 8 + 4];
            float4 b0 = *(const float4*)&Bs[kk][tx * 8];
            float4 b1 = *(const float4*)&Bs[kk][tx * 8 + 4];
            ra[0] = a0.x; ra[1] = a0.y; ra[2] = a0.z; ra[3] = a0.w;
            ra[4] = a1.x; ra[5] = a1.y; ra[6] = a1.z; ra[7] = a1.w;
            rb[0] = b0.x; rb[1] = b0.y; rb[2] = b0.z; rb[3] = b0.w;
            rb[4] = b1.x; rb[5] = b1.y; rb[6] = b1.z; rb[7] = b1.w;
#pragma unroll
            for (int i = 0; i < 8; i++)
#pragma unroll
                for (int j = 0; j < 8; j++)
                    acc[i][j] = fmaf(ra[i], rb[j], acc[i][j]);
        }
    }

    if (MODE == 0) {
        // scatter into Q/K/V [B,H,T,D]
#pragma unroll
        for (int i = 0; i < 8; i++) {
            const int m = bm + ty * 8 + i;
            const int bb = m >> 11;        // /2048
            const int tt = m & 2047;
#pragma unroll
            for (int j = 0; j < 8; j++) {
                const int n = bn + tx * 8 + j;
                const int sel = n >> 10;   // 0=q 1=k 2=v
                const int c = n & 1023;
                const int hh = c >> 6;
                const int dd = c & 63;
                float* dst = (sel == 0) ? g_Q : (sel == 1 ? g_K : g_V);
                dst[(((size_t)bb * HH + hh) * TT + tt) * DD + dd] = acc[i][j];
            }
        }
    } else {
#pragma unroll
        for (int i = 0; i < 8; i++) {
            const int m = bm + ty * 8 + i;
#pragma unroll
            for (int j = 0; j < 8; j++) {
                const int n = bn + tx * 8 + j;
                C[(size_t)m * N + n] = acc[i][j];
            }
        }
    }
}

// ---------------------------------------------------------------------------
// Flash attention (fp32, causal). Block: 32 q-rows of one (b,h).
// grid = (T/32, B*H), 256 threads.
// ---------------------------------------------------------------------------
__global__ __launch_bounds__(256) void attn_kernel()
{
    const int bh = blockIdx.y;
    const int b = bh >> 4;
    const int h = bh & 15;
    const int qi = blockIdx.x;
    const int q0 = qi * 32;

    __shared__ float Qs[32][65];
    __shared__ float Ks[32][65];
    __shared__ float Vs[32][68];
    __shared__ float Ps[32][33];
    __shared__ float sm_m[32], sm_l[32], sm_scale[32];

    const int tid = threadIdx.x;
    const size_t head_off = ((size_t)b * HH + h) * TT * DD;
    const float* Qg = g_Q + head_off;
    const float* Kg = g_K + head_off;
    const float* Vg = g_V + head_off;

    // Load Q tile (32x64), coalesced
#pragma unroll
    for (int r = 0; r < 8; r++) {
        const int e = tid + r * 256;
        const int row = e >> 6;
        const int d = e & 63;
        Qs[row][d] = Qg[(size_t)(q0 + row) * DD + d];
    }
    if (tid < 32) {
        sm_m[tid] = -INFINITY;
        sm_l[tid] = 0.0f;
    }

    float acc[8];
#pragma unroll
    for (int i = 0; i < 8; i++) acc[i] = 0.0f;

    const int d0 = (tid & 15) * 4;  // owned d range (float4)
    const int i0 = tid >> 4;        // owned rows: i0 and i0+16
    const int sj = tid & 31;        // S column
    const int sib = tid >> 5;       // S row base (0..7)

    for (int j0t = 0; j0t <= qi; j0t++) {
        const int k0 = j0t * 32;
        __syncthreads();  // prior consumers of Ks/Vs/Ps done

        // Load K,V tiles (each 32x64)
#pragma unroll
        for (int r = 0; r < 8; r++) {
            const int e = tid + r * 256;
            const int row = e >> 6;
            const int d = e & 63;
            Ks[row][d] = Kg[(size_t)(k0 + row) * DD + d];
            Vs[row][d] = Vg[(size_t)(k0 + row) * DD + d];
        }
        __syncthreads();

        // S = Q K^T * scale, causal mask; each thread 4 entries
#pragma unroll
        for (int r = 0; r < 4; r++) {
            const int i = sib + r * 8;
            float s = 0.0f;
#pragma unroll
            for (int d = 0; d < 64; d++)
                s = fmaf(Qs[i][d], Ks[sj][d], s);
            s *= 0.125f;  // 1/sqrt(64)
            if (k0 + sj > q0 + i) s = -1e30f;
            Ps[i][sj] = s;
        }
        __syncthreads();

        // Online softmax per row (threads 0..31)
        if (tid < 32) {
            const int i = tid;
            const float mold = sm_m[i];
            float mx = mold;
#pragma unroll
            for (int j = 0; j < 32; j++) mx = fmaxf(mx, Ps[i][j]);
            const float scale = __expf(mold - mx);
            float l = sm_l[i] * scale;
#pragma unroll
            for (int j = 0; j < 32; j++) {
                const float p = __expf(Ps[i][j] - mx);
                Ps[i][j] = p;
                l += p;
            }
            sm_m[i] = mx;
            sm_l[i] = l;
            sm_scale[i] = scale;
        }
        __syncthreads();

        // acc = acc*scale + P @ V  (thread owns rows i0, i0+16; cols d0..d0+3)
#pragma unroll
        for (int half = 0; half < 2; half++) {
            const int i = i0 + half * 16;
            const float sc = sm_scale[i];
            float a0 = acc[half * 4 + 0] * sc;
            float a1 = acc[half * 4 + 1] * sc;
            float a2 = acc[half * 4 + 2] * sc;
            float a3 = acc[half * 4 + 3] * sc;
#pragma unroll
            for (int j = 0; j < 32; j++) {
                const float p = Ps[i][j];
                const float4 v = *(const float4*)&Vs[j][d0];
                a0 = fmaf(p, v.x, a0);
                a1 = fmaf(p, v.y, a1);
                a2 = fmaf(p, v.z, a2);
                a3 = fmaf(p, v.w, a3);
            }
            acc[half * 4 + 0] = a0;
            acc[half * 4 + 1] = a1;
            acc[half * 4 + 2] = a2;
            acc[half * 4 + 3] = a3;
        }
    }

    // Write y in [B,T,C] layout
#pragma unroll
    for (int half = 0; half < 2; half++) {
        const int i = i0 + half * 16;
        const float inv = 1.0f / sm_l[i];
        const int t = q0 + i;
        float* outp = g_Y + ((size_t)b * TT + t) * CC + h * DD + d0;
        float4 o;
        o.x = acc[half * 4 + 0] * inv;
        o.y = acc[half * 4 + 1] * inv;
        o.z = acc[half * 4 + 2] * inv;
        o.w = acc[half * 4 + 3] * inv;
        *(float4*)outp = o;
    }
}

// ---------------------------------------------------------------------------
extern "C" void kernel_launch(void* const* d_in, const int* in_sizes, int n_in,
                              void* d_out, int out_size)
{
    const float* x = (const float*)d_in[0];       // [B,T,C]
    const float* W_attn = (const float*)d_in[1];  // [C,3C]
    const float* W_proj = (const float*)d_in[2];  // [C,C]
    float* out = (float*)d_out;                   // [B,T,C]

    (void)in_sizes; (void)n_in; (void)out_size;

    void* yptr = nullptr;
    cudaGetSymbolAddress(&yptr, g_Y);  // pure query, capture-safe

    // 1) QKV projection with scatter into Q/K/V
    {
        dim3 grid(3 * CC / 128, MTOT / 128);  // (24, 64)
        sgemm_kernel<0><<<grid, 256>>>(x, W_attn, nullptr, MTOT, 3 * CC, CC);
    }
    // 2) Causal flash attention -> g_Y [B,T,C]
    {
        dim3 grid(TT / 32, BB * HH);  // (64, 64)
        attn_kernel<<<grid, 256>>>();
    }
    // 3) Output projection
    {
        dim3 grid(CC / 128, MTOT / 128);  // (8, 64)
        sgemm_kernel<1><<<grid, 256>>>((const float*)yptr, W_proj, out,
                                       MTOT, CC, CC);
    }
}

// round 2
// speedup vs baseline: 3.9182x; 3.9182x over previous
#include <cuda_runtime.h>
#include <math.h>

// Problem constants
#define BB 4
#define TT 2048
#define CC 1024
#define HH 16
#define DD 64
#define MTOT (BB * TT)          // 8192

// Scratch (allocation is banned -> __device__ globals)
__device__ float g_Q[BB * HH * TT * DD];
__device__ float g_K[BB * HH * TT * DD];
__device__ float g_V[BB * HH * TT * DD];
__device__ float g_Y[BB * TT * CC];

// ---------------------------------------------------------------------------
// TF32 helpers
// ---------------------------------------------------------------------------
__device__ __forceinline__ unsigned f2tf(float x) {
    unsigned u;
    asm("cvt.rna.tf32.f32 %0, %1;" : "=r"(u) : "f"(x));
    return u;
}
__device__ __forceinline__ float tf32f(float x) { return __uint_as_float(f2tf(x)); }

// D = A(m16k8,row) * B(k8n8,col) + D, tf32 inputs, f32 accum
__device__ __forceinline__ void mma8(float* c, const unsigned* a, const unsigned* b) {
    asm volatile(
        "mma.sync.aligned.m16n8k8.row.col.f32.tf32.tf32.f32 "
        "{%0,%1,%2,%3}, {%4,%5,%6,%7}, {%8,%9}, {%0,%1,%2,%3};\n"
        : "+f"(c[0]), "+f"(c[1]), "+f"(c[2]), "+f"(c[3])
        : "r"(a[0]), "r"(a[1]), "r"(a[2]), "r"(a[3]), "r"(b[0]), "r"(b[1]));
}

// ---------------------------------------------------------------------------
// TF32 tensor-core GEMM: C[M,N] = A[M,K] @ B[K,N]
// 128x128 block, BK=16, 256 threads (8 warps, 4x2; warp tile 32x64).
// MODE 0: scatter epilogue into g_Q/g_K/g_V ([B,H,T,D]); MODE 1: plain store.
// ---------------------------------------------------------------------------
template <int MODE>
__global__ __launch_bounds__(256) void gemm_tf32(
    const float* __restrict__ A, const float* __restrict__ Bm,
    float* __restrict__ C, int M, int N, int K)
{
    __shared__ float As[128][20];    // m-major, pad -> frag banks 4g+r (distinct)
    __shared__ float Bs[16][136];    // k-major, pad -> frag banks 8r+g (distinct)

    const int tid = threadIdx.x;
    const int bm = blockIdx.y * 128;
    const int bn = blockIdx.x * 128;
    const int lane = tid & 31, wid = tid >> 5;
    const int wm = (wid & 3) * 32;   // warp m offset
    const int wn = (wid >> 2) * 64;  // warp n offset
    const int g = lane >> 2, r = lane & 3;

    // Loader assignments
    const int am = tid >> 2;               // A rows am, am+64
    const int aq = (tid & 3) * 4;          // A col quad
    const int bk = tid >> 5;               // B rows bk, bk+8
    const int bq = (tid & 31) * 4;         // B col quad

    const float* Ap0 = A + (size_t)(bm + am) * K + aq;
    const float* Ap1 = A + (size_t)(bm + am + 64) * K + aq;
    const float* Bp0 = Bm + (size_t)bk * N + bn + bq;
    const float* Bp1 = Bm + (size_t)(bk + 8) * N + bn + bq;

    float acc[2][8][4];
#pragma unroll
    for (int mi = 0; mi < 2; mi++)
#pragma unroll
        for (int nj = 0; nj < 8; nj++)
#pragma unroll
            for (int c = 0; c < 4; c++) acc[mi][nj][c] = 0.0f;

    float4 a0r = *(const float4*)Ap0;
    float4 a1r = *(const float4*)Ap1;
    float4 b0r = *(const float4*)Bp0;
    float4 b1r = *(const float4*)Bp1;

    for (int k0 = 0; k0 < K; k0 += 16) {
        __syncthreads();
        As[am][aq + 0] = tf32f(a0r.x); As[am][aq + 1] = tf32f(a0r.y);
        As[am][aq + 2] = tf32f(a0r.z); As[am][aq + 3] = tf32f(a0r.w);
        As[am + 64][aq + 0] = tf32f(a1r.x); As[am + 64][aq + 1] = tf32f(a1r.y);
        As[am + 64][aq + 2] = tf32f(a1r.z); As[am + 64][aq + 3] = tf32f(a1r.w);
        Bs[bk][bq + 0] = tf32f(b0r.x); Bs[bk][bq + 1] = tf32f(b0r.y);
        Bs[bk][bq + 2] = tf32f(b0r.z); Bs[bk][bq + 3] = tf32f(b0r.w);
        Bs[bk + 8][bq + 0] = tf32f(b1r.x); Bs[bk + 8][bq + 1] = tf32f(b1r.y);
        Bs[bk + 8][bq + 2] = tf32f(b1r.z); Bs[bk + 8][bq + 3] = tf32f(b1r.w);
        __syncthreads();

        if (k0 + 16 < K) {
            a0r = *(const float4*)(Ap0 + k0 + 16);
            a1r = *(const float4*)(Ap1 + k0 + 16);
            b0r = *(const float4*)(Bp0 + (size_t)(k0 + 16) * N);
            b1r = *(const float4*)(Bp1 + (size_t)(k0 + 16) * N);
        }

#pragma unroll
        for (int ks = 0; ks < 2; ks++) {
            const int kk = ks * 8;
            unsigned af[2][4];
#pragma unroll
            for (int mi = 0; mi < 2; mi++) {
                const int m0 = wm + 16 * mi;
                af[mi][0] = __float_as_uint(As[m0 + g][kk + r]);
                af[mi][1] = __float_as_uint(As[m0 + g + 8][kk + r]);
                af[mi][2] = __float_as_uint(As[m0 + g][kk + 4 + r]);
                af[mi][3] = __float_as_uint(As[m0 + g + 8][kk + 4 + r]);
            }
#pragma unroll
            for (int nj = 0; nj < 8; nj++) {
                unsigned bf[2];
                bf[0] = __float_as_uint(Bs[kk + r][wn + 8 * nj + g]);
                bf[1] = __float_as_uint(Bs[kk + 4 + r][wn + 8 * nj + g]);
                mma8(acc[0][nj], af[0], bf);
                mma8(acc[1][nj], af[1], bf);
            }
        }
    }

    // Epilogue
#pragma unroll
    for (int mi = 0; mi < 2; mi++) {
        const int mA = bm + wm + 16 * mi + g;     // rows mA (c0,c1), mA+8 (c2,c3)
        if (MODE == 0) {
            const int bb = mA >> 11;
            const int ttA = mA & 2047;
#pragma unroll
            for (int nj = 0; nj < 8; nj++) {
                const int n = bn + wn + 8 * nj + 2 * r;
                const int sel = n >> 10;
                const int c = n & 1023;
                const int hh = c >> 6;
                const int dd = c & 63;
                float* dst = (sel == 0) ? g_Q : (sel == 1 ? g_K : g_V);
                float* base = dst + (((size_t)bb * HH + hh) * TT) * DD + dd;
                float2 v0 = make_float2(acc[mi][nj][0], acc[mi][nj][1]);
                float2 v1 = make_float2(acc[mi][nj][2], acc[mi][nj][3]);
                *(float2*)(base + (size_t)ttA * DD) = v0;
                *(float2*)(base + (size_t)(ttA + 8) * DD) = v1;
            }
        } else {
#pragma unroll
            for (int nj = 0; nj < 8; nj++) {
                const int n = bn + wn + 8 * nj + 2 * r;
                float2 v0 = make_float2(acc[mi][nj][0], acc[mi][nj][1]);
                float2 v1 = make_float2(acc[mi][nj][2], acc[mi][nj][3]);
                *(float2*)&C[(size_t)mA * N + n] = v0;
                *(float2*)&C[(size_t)(mA + 8) * N + n] = v1;
            }
        }
    }
}

// ---------------------------------------------------------------------------
// Flash attention, tf32 MMA. Block = 64 q-rows of one (b,h), 4 warps.
// KV tiles of 64. Warp owns 16 q-rows. Online softmax in log2 domain.
// ---------------------------------------------------------------------------
#define SC_LOG2E 0.18033688f  // (1/sqrt(64)) * log2(e)
#define FULLM 0xffffffffu

__global__ __launch_bounds__(128) void attn_mma_kernel()
{
    const int bh = blockIdx.y;
    const int b = bh >> 4, h = bh & 15;
    const int qi = blockIdx.x;
    const int q0 = qi * 64;
    const int tid = threadIdx.x;
    const int w = tid >> 5, lane = tid & 31;
    const int g = lane >> 2, r = lane & 3;

    __shared__ float Ks[64][68];  // frag banks 4g+r  (68 mod 32 == 4)
    __shared__ float Vs[64][72];  // frag banks 8r+g  (72 mod 32 == 8)

    const size_t hoff = ((size_t)b * HH + h) * TT * DD;
    const float* Qg = g_Q + hoff;
    const float* Kg = g_K + hoff;
    const float* Vg = g_V + hoff;

    // Stage Q (64x64) into Ks buffer, build register-resident Q fragments
    for (int e = tid; e < 1024; e += 128) {
        const int row = e >> 4, c4 = (e & 15) * 4;
        float4 v = *(const float4*)&Qg[(size_t)(q0 + row) * DD + c4];
        Ks[row][c4 + 0] = tf32f(v.x); Ks[row][c4 + 1] = tf32f(v.y);
        Ks[row][c4 + 2] = tf32f(v.z); Ks[row][c4 + 3] = tf32f(v.w);
    }
    __syncthreads();

    unsigned qf[8][4];
    const int mrow = 16 * w + g;
#pragma unroll
    for (int ks = 0; ks < 8; ks++) {
        qf[ks][0] = __float_as_uint(Ks[mrow][8 * ks + r]);
        qf[ks][1] = __float_as_uint(Ks[mrow + 8][8 * ks + r]);
        qf[ks][2] = __float_as_uint(Ks[mrow][8 * ks + 4 + r]);
        qf[ks][3] = __float_as_uint(Ks[mrow + 8][8 * ks + 4 + r]);
    }

    float oacc[8][4];
#pragma unroll
    for (int dt = 0; dt < 8; dt++)
#pragma unroll
        for (int c = 0; c < 4; c++) oacc[dt][c] = 0.0f;
    float mA = -1e30f, mB = -1e30f, lA = 0.0f, lB = 0.0f;

    const int qA = q0 + 16 * w + g;
    const int qB = qA + 8;

    for (int j0 = 0; j0 <= qi; j0++) {
        const int kv0 = j0 * 64;
        __syncthreads();
        for (int e = tid; e < 1024; e += 128) {
            const int row = e >> 4, c4 = (e & 15) * 4;
            float4 kv = *(const float4*)&Kg[(size_t)(kv0 + row) * DD + c4];
            float4 vv = *(const float4*)&Vg[(size_t)(kv0 + row) * DD + c4];
            Ks[row][c4 + 0] = tf32f(kv.x); Ks[row][c4 + 1] = tf32f(kv.y);
            Ks[row][c4 + 2] = tf32f(kv.z); Ks[row][c4 + 3] = tf32f(kv.w);
            Vs[row][c4 + 0] = tf32f(vv.x); Vs[row][c4 + 1] = tf32f(vv.y);
            Vs[row][c4 + 2] = tf32f(vv.z); Vs[row][c4 + 3] = tf32f(vv.w);
        }
        __syncthreads();

        // S = Q K^T  (warp: 16 x 64)
        float sacc[8][4];
#pragma unroll
        for (int j = 0; j < 8; j++) {
#pragma unroll
            for (int c = 0; c < 4; c++) sacc[j][c] = 0.0f;
#pragma unroll
            for (int ks = 0; ks < 8; ks++) {
                unsigned bf[2];
                bf[0] = __float_as_uint(Ks[8 * j + g][8 * ks + r]);
                bf[1] = __float_as_uint(Ks[8 * j + g][8 * ks + 4 + r]);
                mma8(sacc[j], qf[ks], bf);
            }
        }

        // scale to log2 domain + causal mask, track tile row max
        const bool diag = (j0 == qi);
        float tmA = -1e30f, tmB = -1e30f;
#pragma unroll
        for (int j = 0; j < 8; j++) {
            const int kc = kv0 + 8 * j + 2 * r;
            float t0 = sacc[j][0] * SC_LOG2E;
            float t1 = sacc[j][1] * SC_LOG2E;
            float t2 = sacc[j][2] * SC_LOG2E;
            float t3 = sacc[j][3] * SC_LOG2E;
            if (diag) {
                if (kc > qA) t0 = -1e30f;
                if (kc + 1 > qA) t1 = -1e30f;
                if (kc > qB) t2 = -1e30f;
                if (kc + 1 > qB) t3 = -1e30f;
            }
            sacc[j][0] = t0; sacc[j][1] = t1; sacc[j][2] = t2; sacc[j][3] = t3;
            tmA = fmaxf(tmA, fmaxf(t0, t1));
            tmB = fmaxf(tmB, fmaxf(t2, t3));
        }
        tmA = fmaxf(tmA, __shfl_xor_sync(FULLM, tmA, 1));
        tmA = fmaxf(tmA, __shfl_xor_sync(FULLM, tmA, 2));
        tmB = fmaxf(tmB, __shfl_xor_sync(FULLM, tmB, 1));
        tmB = fmaxf(tmB, __shfl_xor_sync(FULLM, tmB, 2));

        const float mnA = fmaxf(mA, tmA);
        const float mnB = fmaxf(mB, tmB);
        const float scA = exp2f(mA - mnA);
        const float scB = exp2f(mB - mnB);
        mA = mnA; mB = mnB;

        // exponentiate (tf32-rounded so l matches the PV numerator), row sums
        float smA = 0.0f, smB = 0.0f;
#pragma unroll
        for (int j = 0; j < 8; j++) {
            float p0 = tf32f(exp2f(sacc[j][0] - mA));
            float p1 = tf32f(exp2f(sacc[j][1] - mA));
            float p2 = tf32f(exp2f(sacc[j][2] - mB));
            float p3 = tf32f(exp2f(sacc[j][3] - mB));
            sacc[j][0] = p0; sacc[j][1] = p1; sacc[j][2] = p2; sacc[j][3] = p3;
            smA += p0 + p1;
            smB += p2 + p3;
        }
        smA += __shfl_xor_sync(FULLM, smA, 1);
        smA += __shfl_xor_sync(FULLM, smA, 2);
        smB += __shfl_xor_sync(FULLM, smB, 1);
        smB += __shfl_xor_sync(FULLM, smB, 2);
        lA = lA * scA + smA;
        lB = lB * scB + smB;

        // rescale O
#pragma unroll
        for (int dt = 0; dt < 8; dt++) {
            oacc[dt][0] *= scA; oacc[dt][1] *= scA;
            oacc[dt][2] *= scB; oacc[dt][3] *= scB;
        }

        // O += P @ V  (P: C-frag -> A-frag via shfl)
        const int s0 = (lane & ~3) | (r >> 1);
        const int s1 = s0 + 2;
        const bool odd = (r & 1);
#pragma unroll
        for (int ks = 0; ks < 8; ks++) {
            float p00 = __shfl_sync(FULLM, sacc[ks][0], s0);
            float p01 = __shfl_sync(FULLM, sacc[ks][1], s0);
            float p02 = __shfl_sync(FULLM, sacc[ks][2], s0);
            float p03 = __shfl_sync(FULLM, sacc[ks][3], s0);
            float p10 = __shfl_sync(FULLM, sacc[ks][0], s1);
            float p11 = __shfl_sync(FULLM, sacc[ks][1], s1);
            float p12 = __shfl_sync(FULLM, sacc[ks][2], s1);
            float p13 = __shfl_sync(FULLM, sacc[ks][3], s1);
            unsigned pf[4];
            pf[0] = __float_as_uint(odd ? p01 : p00);
            pf[1] = __float_as_uint(odd ? p03 : p02);
            pf[2] = __float_as_uint(odd ? p11 : p10);
            pf[3] = __float_as_uint(odd ? p13 : p12);
#pragma unroll
            for (int dt = 0; dt < 8; dt++) {
                unsigned bf[2];
                bf[0] = __float_as_uint(Vs[8 * ks + r][8 * dt + g]);
                bf[1] = __float_as_uint(Vs[8 * ks + 4 + r][8 * dt + g]);
                mma8(oacc[dt], pf, bf);
            }
        }
    }

    // Epilogue: y[b, t, h*64 + d]
    const float ivA = 1.0f / lA;
    const float ivB = 1.0f / lB;
    float* yA = g_Y + ((size_t)b * TT + qA) * CC + h * DD;
    float* yB = g_Y + ((size_t)b * TT + qB) * CC + h * DD;
#pragma unroll
    for (int dt = 0; dt < 8; dt++) {
        const int d = 8 * dt + 2 * r;
        *(float2*)(yA + d) = make_float2(oacc[dt][0] * ivA, oacc[dt][1] * ivA);
        *(float2*)(yB + d) = make_float2(oacc[dt][2] * ivB, oacc[dt][3] * ivB);
    }
}

// ---------------------------------------------------------------------------
extern "C" void kernel_launch(void* const* d_in, const int* in_sizes, int n_in,
                              void* d_out, int out_size)
{
    const float* x = (const float*)d_in[0];       // [B,T,C]
    const float* W_attn = (const float*)d_in[1];  // [C,3C]
    const float* W_proj = (const float*)d_in[2];  // [C,C]
    float* out = (float*)d_out;                   // [B,T,C]

    (void)in_sizes; (void)n_in; (void)out_size;

    void* yptr = nullptr;
    cudaGetSymbolAddress(&yptr, g_Y);  // pure query, capture-safe

    // 1) QKV projection (tf32 MMA) with scatter into Q/K/V
    {
        dim3 grid(3 * CC / 128, MTOT / 128);  // (24, 64)
        gemm_tf32<0><<<grid, 256>>>(x, W_attn, nullptr, MTOT, 3 * CC, CC);
    }
    // 2) Causal flash attention (tf32 MMA) -> g_Y [B,T,C]
    {
        dim3 grid(TT / 64, BB * HH);  // (32, 64)
        attn_mma_kernel<<<grid, 128>>>();
    }
    // 3) Output projection (tf32 MMA)
    {
        dim3 grid(CC / 128, MTOT / 128);  // (8, 64)
        gemm_tf32<1><<<grid, 256>>>((const float*)yptr, W_proj, out,
                                    MTOT, CC, CC);
    }
}